// round 1
// baseline (speedup 1.0000x reference)
#include <cuda_runtime.h>

// Problem constants (GENConv_137438953767)
constexpr int CN = 50000;     // nodes
constexpr int CE = 800000;    // edges
constexpr int D = 64;
constexpr int NBOND = 9;
constexpr float EPS = 1e-7f;

// Scratch (device globals; no allocation allowed)
__device__ int g_count[CN];
__device__ int g_cursor[CN];
__device__ int g_rowstart[CN + 1];
__device__ int g_bsum[128];
__device__ unsigned g_sorted[CE];   // packed: src (low 16 bits) | attr<<16

// ---------------------------------------------------------------------------
__global__ void k_clear(int n) {
    int i = blockIdx.x * blockDim.x + threadIdx.x;
    if (i < n) { g_count[i] = 0; g_cursor[i] = 0; }
}

__global__ void k_hist(const int* __restrict__ dst, int e) {
    int i = blockIdx.x * blockDim.x + threadIdx.x;
    if (i < e) atomicAdd(&g_count[dst[i]], 1);
}

// Per-block inclusive scan (512), write exclusive per-element + block sum.
__global__ void k_scan1(int n) {
    __shared__ int sh[512];
    int i = blockIdx.x * 512 + threadIdx.x;
    int v = (i < n) ? g_count[i] : 0;
    sh[threadIdx.x] = v;
    __syncthreads();
    #pragma unroll
    for (int off = 1; off < 512; off <<= 1) {
        int t = (threadIdx.x >= off) ? sh[threadIdx.x - off] : 0;
        __syncthreads();
        sh[threadIdx.x] += t;
        __syncthreads();
    }
    if (i < n) g_rowstart[i] = sh[threadIdx.x] - v;   // exclusive
    if (threadIdx.x == 511) g_bsum[blockIdx.x] = sh[511];
}

// Exclusive scan of block sums (nblk <= 128) in one block.
__global__ void k_scan2(int nblk) {
    __shared__ int sh[128];
    int t = threadIdx.x;
    int v = (t < nblk) ? g_bsum[t] : 0;
    sh[t] = v;
    __syncthreads();
    #pragma unroll
    for (int off = 1; off < 128; off <<= 1) {
        int x = (t >= off) ? sh[t - off] : 0;
        __syncthreads();
        sh[t] += x;
        __syncthreads();
    }
    if (t < nblk) g_bsum[t] = sh[t] - v;   // exclusive
}

__global__ void k_scan3(int n, int e) {
    int i = blockIdx.x * blockDim.x + threadIdx.x;
    if (i < n) g_rowstart[i] += g_bsum[i >> 9];
    if (i == 0) g_rowstart[n] = e;
}

__global__ void k_scatter(const int* __restrict__ src, const int* __restrict__ dst,
                          const int* __restrict__ attr, int e) {
    int i = blockIdx.x * blockDim.x + threadIdx.x;
    if (i < e) {
        int d0 = dst[i];
        int pos = g_rowstart[d0] + atomicAdd(&g_cursor[d0], 1);
        g_sorted[pos] = (unsigned)src[i] | ((unsigned)attr[i] << 16);
    }
}

// ---------------------------------------------------------------------------
// Main fused kernel: warp-per-node segment softmax aggregation + output GEMM.
// out[n] = (x[n] + sum_e m_e * exp(m_e) / sum_e exp(m_e)) @ W^T + b
__global__ __launch_bounds__(1024) void k_main(
    const float* __restrict__ nf,
    const float* __restrict__ emb,
    const float* __restrict__ W,
    const float* __restrict__ bias,
    float* __restrict__ out,
    int n)
{
    __shared__ float shWt[64 * 65];        // W^T with pad-65: conflict-free both ways
    __shared__ float shEmb[NBOND * 64];
    __shared__ float shB[64];
    __shared__ float shF[32 * 64];         // one feats row per warp

    int tid = threadIdx.x;
    for (int idx = tid; idx < 64 * 64; idx += 1024) {
        int j = idx >> 6, k = idx & 63;
        shWt[k * 65 + j] = W[idx];         // store banks (k+j)%32: conflict-free
    }
    for (int idx = tid; idx < NBOND * 64; idx += 1024) shEmb[idx] = emb[idx];
    if (tid < 64) shB[tid] = bias[tid];
    __syncthreads();

    int warp = tid >> 5, lane = tid & 31;
    int node = blockIdx.x * 32 + warp;
    if (node >= n) return;

    int beg = g_rowstart[node];
    int end = g_rowstart[node + 1];

    float num0 = 0.f, num1 = 0.f, den0 = 0.f, den1 = 0.f;

    for (int base = beg; base < end; base += 32) {
        int cnt = min(32, end - base);
        unsigned pk = 0;
        if (lane < cnt) pk = g_sorted[base + lane];
        #pragma unroll 4
        for (int j = 0; j < cnt; j++) {
            unsigned p = __shfl_sync(0xffffffffu, pk, j);
            int s = (int)(p & 0xffffu);
            int a = (int)(p >> 16);
            float2 x  = *(const float2*)(nf + s * 64 + 2 * lane);
            float2 em = *(const float2*)(shEmb + a * 64 + 2 * lane);
            float m0 = fmaxf(x.x + em.x, 0.f) + EPS;
            float m1 = fmaxf(x.y + em.y, 0.f) + EPS;
            float z0 = __expf(m0);
            float z1 = __expf(m1);
            den0 += z0; den1 += z1;
            num0 += m0 * z0; num1 += m1 * z1;
        }
    }

    float2 xn = *(const float2*)(nf + node * 64 + 2 * lane);
    float f0 = xn.x, f1 = xn.y;
    if (end > beg) {
        f0 += num0 / den0;
        f1 += num1 / den1;
    }
    float* fw = shF + warp * 64;
    *(float2*)(fw + 2 * lane) = make_float2(f0, f1);
    __syncwarp();

    // GEMM: lane computes output cols (lane, lane+32)
    int c0 = lane, c1 = lane + 32;
    float o0 = shB[c0], o1 = shB[c1];
    #pragma unroll
    for (int k = 0; k < 64; k++) {
        float f = fw[k];                        // broadcast
        o0 += f * shWt[k * 65 + c0];            // banks (k+lane)%32
        o1 += f * shWt[k * 65 + c1];            // same, conflict-free
    }
    out[node * 64 + c0] = o0;
    out[node * 64 + c1] = o1;
}

// ---------------------------------------------------------------------------
extern "C" void kernel_launch(void* const* d_in, const int* in_sizes, int n_in,
                              void* d_out, int out_size) {
    const float* nf   = (const float*)d_in[0];  // node_feats (N,64)
    const int*   attr = (const int*)  d_in[1];  // edge_attr (E,1)
    const int*   src  = (const int*)  d_in[2];  // src (E)
    const int*   dst  = (const int*)  d_in[3];  // dst (E)
    const float* emb  = (const float*)d_in[4];  // emb_table (9,64)
    const float* W    = (const float*)d_in[5];  // W (64,64)
    const float* b    = (const float*)d_in[6];  // b (64)
    float* out = (float*)d_out;

    int n = in_sizes[0] / D;    // 50000
    int e = in_sizes[2];        // 800000

    k_clear  <<<(n + 255) / 256, 256>>>(n);
    k_hist   <<<(e + 255) / 256, 256>>>(dst, e);
    int nblk = (n + 511) / 512;
    k_scan1  <<<nblk, 512>>>(n);
    k_scan2  <<<1, 128>>>(nblk);
    k_scan3  <<<(n + 255) / 256, 256>>>(n, e);
    k_scatter<<<(e + 255) / 256, 256>>>(src, dst, attr, e);
    k_main   <<<(n + 31) / 32, 1024>>>(nf, emb, W, b, out, n);
}